// round 3
// baseline (speedup 1.0000x reference)
#include <cuda_runtime.h>
#include <cstdint>
#include <cstddef>

#define B_ 8
#define N_ 8192
#define D_ 256
#define KCH 16
#define ROWS_PER_CHUNK (N_ / KCH)   // 512
#define KB 16

typedef unsigned long long ull;

// ---------------- device scratch (no allocations allowed) ----------------
__device__ float g_S[B_ * D_ * D_];    // S[b] = key_m^T @ value  (masked gram)
__device__ float g_T1[B_ * D_ * D_];   // T1[b] = Wk @ S[b]
__device__ float g_A[B_ * D_ * D_];    // logits, then softmax in-place (aw)
__device__ float g_M[B_ * D_ * D_];    // M[b] = Wq^T @ aw[b]
__device__ float g_rk[B_ * D_];        // sum_n m*key
__device__ float g_rv[B_ * D_];        // sum_n m*value
__device__ float g_u[B_ * D_];         // Wk @ rk
__device__ float g_w[B_ * D_];         // Wv @ rv
__device__ float g_t[B_ * D_];         // bq^T @ aw
__device__ float g_cm[B_];             // sum_n m
__device__ int   g_kind;               // 0 = byte mask, 1 = word mask
__device__ float g_m[B_ * N_];         // canonical mask: 1=keep, 0=padded

// ---------------- f32x2 packed helpers (sm_103a) ----------------
__device__ __forceinline__ ull pack2(float lo, float hi) {
    ull r; asm("mov.b64 %0, {%1,%2};" : "=l"(r) : "f"(lo), "f"(hi)); return r;
}
__device__ __forceinline__ void unpack2(ull v, float& lo, float& hi) {
    asm("mov.b64 {%0,%1}, %2;" : "=f"(lo), "=f"(hi) : "l"(v));
}
__device__ __forceinline__ ull ffma2(ull a, ull b, ull c) {
    ull d; asm("fma.rn.f32x2 %0, %1, %2, %3;" : "=l"(d) : "l"(a), "l"(b), "l"(c)); return d;
}

// ---------------- mask dtype detection + canonicalization ----------------
// Scan the first 65536 bytes of the mask buffer (safe for all candidate dtypes:
// bool8 buffer is exactly 65536 B, int32/f32 buffers are 256 KiB).
// bool8 mask: value 1 appears at byte offsets of every residue mod 4.
// int32/f32 mask (0/1 or 0.0/1.0 little-endian): byte offset %4==1 is ALWAYS 0.
__global__ void k_detect(const unsigned char* __restrict__ raw) {
    __shared__ int s1;
    if (threadIdx.x == 0) s1 = 0;
    __syncthreads();
    int local = 0;
    for (int i = threadIdx.x; i < 65536; i += blockDim.x) {
        if ((i & 3) == 1 && raw[i] != 0) local = 1;
    }
    if (local) atomicOr(&s1, 1);
    __syncthreads();
    if (threadIdx.x == 0) g_kind = s1 ? 0 : 1;
}

__global__ void k_maskconv(const void* __restrict__ rawv) {
    int n = blockIdx.x * blockDim.x + threadIdx.x;
    if (n >= B_ * N_) return;
    int kind = g_kind;
    bool padded;
    if (kind == 0) {
        padded = ((const unsigned char*)rawv)[n] != 0;
    } else {
        // works for int32 (1 != 0) and float32 (0x3f800000 != 0) alike
        padded = ((const unsigned int*)rawv)[n] != 0u;
    }
    g_m[n] = padded ? 0.f : 1.f;
}

// ---------------- zero scratch accumulators ----------------
__global__ void k_zero() {
    int i = blockIdx.x * blockDim.x + threadIdx.x;
    if (i < B_ * D_ * D_) g_S[i] = 0.f;
    if (i < B_ * D_) { g_rk[i] = 0.f; g_rv[i] = 0.f; }
    if (i < B_) g_cm[i] = 0.f;
}

// ---------------- k1: S[b] = key_m^T @ value over N, plus rk/rv/cm ----------------
// grid (KCH, 2 slabs, B), 256 threads. CTA output tile: [128 d x 256 e], K-chunk 512 rows.
__global__ void __launch_bounds__(256, 1)
k1_reduce(const float* __restrict__ key, const float* __restrict__ value) {
    const int b = blockIdx.z, slab = blockIdx.y, chunk = blockIdx.x;
    const int tid = threadIdx.x, tx = tid & 15, ty = tid >> 4;
    const int n0 = chunk * ROWS_PER_CHUNK;
    const float* keyb = key + ((size_t)b * N_ + n0) * D_ + slab * 128;
    const float* valb = value + ((size_t)b * N_ + n0) * D_;
    const float* mb = g_m + (size_t)b * N_ + n0;

    __shared__ float sk[KB][128];
    __shared__ float sv[KB][256];
    __shared__ float sm[KB];

    ull acc[8][8];
#pragma unroll
    for (int d = 0; d < 8; d++)
#pragma unroll
        for (int p = 0; p < 8; p++) acc[d][p] = 0ull;

    float ksum = 0.f, vsum = 0.f, msum = 0.f;

    for (int s = 0; s < ROWS_PER_CHUNK / KB; s++) {
        __syncthreads();
        // key slab (masked) : 16 rows x 128 floats = 512 float4
#pragma unroll
        for (int i = 0; i < 2; i++) {
            int idx = tid + 256 * i;
            int r = idx >> 5, q = idx & 31;
            float m = mb[s * KB + r];
            float4 kv = *(const float4*)(keyb + (size_t)(s * KB + r) * D_ + q * 4);
            *(float4*)&sk[r][q * 4] = make_float4(kv.x * m, kv.y * m, kv.z * m, kv.w * m);
            if (q == 0) sm[r] = m;
        }
        // value: 16 rows x 256 floats = 1024 float4
#pragma unroll
        for (int i = 0; i < 4; i++) {
            int idx = tid + 256 * i;
            int r = idx >> 6, q = idx & 63;
            *(float4*)&sv[r][q * 4] = *(const float4*)(valb + (size_t)(s * KB + r) * D_ + q * 4);
        }
        __syncthreads();

#pragma unroll
        for (int kk = 0; kk < KB; kk++) {
            float4 ka = *(const float4*)&sk[kk][ty * 8];
            float4 kb = *(const float4*)&sk[kk][ty * 8 + 4];
            ull k2[8];
            k2[0] = pack2(ka.x, ka.x); k2[1] = pack2(ka.y, ka.y);
            k2[2] = pack2(ka.z, ka.z); k2[3] = pack2(ka.w, ka.w);
            k2[4] = pack2(kb.x, kb.x); k2[5] = pack2(kb.y, kb.y);
            k2[6] = pack2(kb.z, kb.z); k2[7] = pack2(kb.w, kb.w);
            ull v2[8];
#pragma unroll
            for (int p = 0; p < 8; p++) v2[p] = *(const ull*)&sv[kk][2 * tx + 32 * p];
#pragma unroll
            for (int d = 0; d < 8; d++)
#pragma unroll
                for (int p = 0; p < 8; p++)
                    acc[d][p] = ffma2(k2[d], v2[p], acc[d][p]);
        }

        // side sums (bias correction vectors); smem valid until next stage's loads
#pragma unroll
        for (int r = 0; r < KB; r++) {
            vsum += sm[r] * sv[r][tid];
            if (tid < 128) ksum += sk[r][tid];
        }
        if (tid == 0) {
#pragma unroll
            for (int r = 0; r < KB; r++) msum += sm[r];
        }
    }

    float* Sb = g_S + b * D_ * D_;
#pragma unroll
    for (int d = 0; d < 8; d++) {
        int row = slab * 128 + ty * 8 + d;
#pragma unroll
        for (int p = 0; p < 8; p++) {
            float lo, hi; unpack2(acc[d][p], lo, hi);
            int e = 2 * tx + 32 * p;
            atomicAdd(&Sb[row * D_ + e], lo);
            atomicAdd(&Sb[row * D_ + e + 1], hi);
        }
    }
    if (tid < 128) atomicAdd(&g_rk[b * D_ + slab * 128 + tid], ksum);
    if (slab == 0) atomicAdd(&g_rv[b * D_ + tid], vsum);
    if (slab == 0 && tid == 0) atomicAdd(&g_cm[b], msum);
}

// ---------------- k_uw: u = Wk@rk, w = Wv@rv (per batch) ----------------
__global__ void k_uw(const float* __restrict__ Wk, const float* __restrict__ Wv) {
    int b = blockIdx.x, d = threadIdx.x;
    float su = 0.f, sw = 0.f;
    for (int i = 0; i < D_; i++) {
        su += Wk[d * D_ + i] * g_rk[b * D_ + i];
        sw += Wv[d * D_ + i] * g_rv[b * D_ + i];
    }
    g_u[b * D_ + d] = su;
    g_w[b * D_ + d] = sw;
}

// ---------------- k2: T1[b] = Wk @ S[b] ----------------
__global__ void __launch_bounds__(256, 1)
k2_T1(const float* __restrict__ Wk) {
    const int b = blockIdx.y, d0 = blockIdx.x * 16;
    const int tid = threadIdx.x, tx = tid & 15, ty = tid >> 4;
    __shared__ float sA[16][16];
    __shared__ float sB[16][256];
    ull acc[8];
#pragma unroll
    for (int p = 0; p < 8; p++) acc[p] = 0ull;
    const float* Sb = g_S + b * D_ * D_;

    for (int i0 = 0; i0 < D_; i0 += 16) {
        __syncthreads();
        if (tid < 64) {
            int r = tid >> 2, q = tid & 3;
            *(float4*)&sA[r][q * 4] = *(const float4*)(Wk + (size_t)(d0 + r) * D_ + i0 + q * 4);
        }
#pragma unroll
        for (int i = 0; i < 4; i++) {
            int idx = tid + 256 * i;
            int r = idx >> 6, q = idx & 63;
            *(float4*)&sB[r][q * 4] = *(const float4*)(Sb + (size_t)(i0 + r) * D_ + q * 4);
        }
        __syncthreads();
#pragma unroll
        for (int ii = 0; ii < 16; ii++) {
            float a = sA[ty][ii];
            ull a2 = pack2(a, a);
#pragma unroll
            for (int p = 0; p < 8; p++)
                acc[p] = ffma2(a2, *(const ull*)&sB[ii][2 * tx + 32 * p], acc[p]);
        }
    }
    float* T1b = g_T1 + b * D_ * D_;
    int row = d0 + ty;
#pragma unroll
    for (int p = 0; p < 8; p++) {
        float lo, hi; unpack2(acc[p], lo, hi);
        *(float2*)&T1b[row * D_ + 2 * tx + 32 * p] = make_float2(lo, hi);
    }
}

// ---------------- k3: A[b] = (T1[b] @ Wv^T + rank-1 corrections) / sqrt(8) ----------------
__global__ void __launch_bounds__(256, 1)
k3_A(const float* __restrict__ Wv, const float* __restrict__ bk,
     const float* __restrict__ bv) {
    const int b = blockIdx.y, d0 = blockIdx.x * 16;
    const int tid = threadIdx.x, tx = tid & 15, ty = tid >> 4;
    __shared__ float sA[16][16];
    __shared__ float sB[16][258];   // Wv^T staged [j][e], padded (8B-aligned row stride)
    ull acc[8];
#pragma unroll
    for (int p = 0; p < 8; p++) acc[p] = 0ull;
    const float* T1b = g_T1 + b * D_ * D_;

    for (int j0 = 0; j0 < D_; j0 += 16) {
        __syncthreads();
        if (tid < 64) {
            int r = tid >> 2, q = tid & 3;
            *(float4*)&sA[r][q * 4] = *(const float4*)(T1b + (size_t)(d0 + r) * D_ + j0 + q * 4);
        }
#pragma unroll
        for (int i = 0; i < 4; i++) {
            int idx = tid + 256 * i;   // 0..1023
            int q = idx & 3, e = idx >> 2;
            float4 v = *(const float4*)(Wv + (size_t)e * D_ + j0 + q * 4);
            sB[q * 4 + 0][e] = v.x; sB[q * 4 + 1][e] = v.y;
            sB[q * 4 + 2][e] = v.z; sB[q * 4 + 3][e] = v.w;
        }
        __syncthreads();
#pragma unroll
        for (int jj = 0; jj < 16; jj++) {
            float a = sA[ty][jj];
            ull a2 = pack2(a, a);
#pragma unroll
            for (int p = 0; p < 8; p++)
                acc[p] = ffma2(a2, *(const ull*)&sB[jj][2 * tx + 32 * p], acc[p]);
        }
    }
    const int d = d0 + ty;
    const float u_d = g_u[b * D_ + d], bk_d = bk[d], cmv = g_cm[b];
    const float inv = 0.3535533905932738f;  // 1/sqrt(8)
    float* Ab = g_A + b * D_ * D_;
#pragma unroll
    for (int p = 0; p < 8; p++) {
        float lo, hi; unpack2(acc[p], lo, hi);
        int e = 2 * tx + 32 * p;
        float bv0 = bv[e], bv1 = bv[e + 1];
        float w0 = g_w[b * D_ + e], w1 = g_w[b * D_ + e + 1];
        lo = (lo + u_d * bv0 + bk_d * w0 + cmv * bk_d * bv0) * inv;
        hi = (hi + u_d * bv1 + bk_d * w1 + cmv * bk_d * bv1) * inv;
        *(float2*)&Ab[d * D_ + e] = make_float2(lo, hi);
    }
}

// ---------------- k4: column softmax over d (in-place), plus t = bq^T @ aw ----------------
__global__ void k4_softmax(const float* __restrict__ bq) {
    const int b = blockIdx.y;
    const int w = threadIdx.x >> 5, lane = threadIdx.x & 31;
    const int e = blockIdx.x * 8 + w;
    float* col = g_A + b * D_ * D_ + e;
    float v[8];
#pragma unroll
    for (int s = 0; s < 8; s++) v[s] = col[(lane + 32 * s) * D_];
    float mx = v[0];
#pragma unroll
    for (int s = 1; s < 8; s++) mx = fmaxf(mx, v[s]);
#pragma unroll
    for (int o = 16; o > 0; o >>= 1) mx = fmaxf(mx, __shfl_xor_sync(0xffffffffu, mx, o));
    float sum = 0.f;
#pragma unroll
    for (int s = 0; s < 8; s++) { v[s] = expf(v[s] - mx); sum += v[s]; }
#pragma unroll
    for (int o = 16; o > 0; o >>= 1) sum += __shfl_xor_sync(0xffffffffu, sum, o);
    const float isum = 1.f / sum;
    float tacc = 0.f;
#pragma unroll
    for (int s = 0; s < 8; s++) {
        float p = v[s] * isum;
        col[(lane + 32 * s) * D_] = p;
        tacc += p * bq[lane + 32 * s];
    }
#pragma unroll
    for (int o = 16; o > 0; o >>= 1) tacc += __shfl_xor_sync(0xffffffffu, tacc, o);
    if (lane == 0) g_t[b * D_ + e] = tacc;
}

// ---------------- k5: M[b][i][e] = sum_d Wq[d][i] * aw[b][d][e] ----------------
__global__ void __launch_bounds__(256, 1)
k5_M(const float* __restrict__ Wq) {
    const int b = blockIdx.y, i0 = blockIdx.x * 16;
    const int tid = threadIdx.x, tx = tid & 15, ty = tid >> 4;
    __shared__ float sA[16][17];   // [i_local][dd]  (transposed Wq tile)
    __shared__ float sB[16][256];  // aw rows
    ull acc[8];
#pragma unroll
    for (int p = 0; p < 8; p++) acc[p] = 0ull;
    const float* awb = g_A + b * D_ * D_;

    for (int dd0 = 0; dd0 < D_; dd0 += 16) {
        __syncthreads();
        if (tid < 64) {
            int r = tid >> 2, q = tid & 3;   // r = dd, q = i quad
            float4 v = *(const float4*)(Wq + (size_t)(dd0 + r) * D_ + i0 + q * 4);
            sA[q * 4 + 0][r] = v.x; sA[q * 4 + 1][r] = v.y;
            sA[q * 4 + 2][r] = v.z; sA[q * 4 + 3][r] = v.w;
        }
#pragma unroll
        for (int i = 0; i < 4; i++) {
            int idx = tid + 256 * i;
            int r = idx >> 6, q = idx & 63;
            *(float4*)&sB[r][q * 4] = *(const float4*)(awb + (size_t)(dd0 + r) * D_ + q * 4);
        }
        __syncthreads();
#pragma unroll
        for (int dd = 0; dd < 16; dd++) {
            float a = sA[ty][dd];
            ull a2 = pack2(a, a);
#pragma unroll
            for (int p = 0; p < 8; p++)
                acc[p] = ffma2(a2, *(const ull*)&sB[dd][2 * tx + 32 * p], acc[p]);
        }
    }
    float* Mb = g_M + b * D_ * D_;
    int row = i0 + ty;
#pragma unroll
    for (int p = 0; p < 8; p++) {
        float lo, hi; unpack2(acc[p], lo, hi);
        *(float2*)&Mb[row * D_ + 2 * tx + 32 * p] = make_float2(lo, hi);
    }
}

// ---------------- k6: out[b] = query[b] @ M[b] + t[b] ----------------
__global__ void __launch_bounds__(256, 1)
k6_out(const float* __restrict__ query, float* __restrict__ out) {
    const int b = blockIdx.y;
    const int n0 = blockIdx.x * 128;
    const int tid = threadIdx.x, tx = tid & 15, ty = tid >> 4;
    __shared__ float sq[KB][132];    // [d_local][n], padded
    __shared__ float smM[KB][256];
    ull acc[8][8];
#pragma unroll
    for (int d = 0; d < 8; d++)
#pragma unroll
        for (int p = 0; p < 8; p++) acc[d][p] = 0ull;
    const float* qb = query + ((size_t)b * N_ + n0) * D_;
    const float* Mb = g_M + b * D_ * D_;

    for (int d0 = 0; d0 < D_; d0 += 16) {
        __syncthreads();
        // query tile (transposed store): 128 n x 16 d = 512 float4
#pragma unroll
        for (int i = 0; i < 2; i++) {
            int idx = tid + 256 * i;            // 0..511
            int dq = idx & 3, n = idx >> 2;     // n 0..127
            float4 v = *(const float4*)(qb + (size_t)n * D_ + d0 + dq * 4);
            sq[dq * 4 + 0][n] = v.x; sq[dq * 4 + 1][n] = v.y;
            sq[dq * 4 + 2][n] = v.z; sq[dq * 4 + 3][n] = v.w;
        }
        // M tile: 16 rows x 256 = 1024 float4
#pragma unroll
        for (int i = 0; i < 4; i++) {
            int idx = tid + 256 * i;
            int r = idx >> 6, q = idx & 63;
            *(float4*)&smM[r][q * 4] = *(const float4*)(Mb + (size_t)(d0 + r) * D_ + q * 4);
        }
        __syncthreads();
#pragma unroll
        for (int kk = 0; kk < KB; kk++) {
            float4 qa = *(const float4*)&sq[kk][ty * 8];
            float4 qc = *(const float4*)&sq[kk][ty * 8 + 4];
            ull q2[8];
            q2[0] = pack2(qa.x, qa.x); q2[1] = pack2(qa.y, qa.y);
            q2[2] = pack2(qa.z, qa.z); q2[3] = pack2(qa.w, qa.w);
            q2[4] = pack2(qc.x, qc.x); q2[5] = pack2(qc.y, qc.y);
            q2[6] = pack2(qc.z, qc.z); q2[7] = pack2(qc.w, qc.w);
            ull v2[8];
#pragma unroll
            for (int p = 0; p < 8; p++) v2[p] = *(const ull*)&smM[kk][2 * tx + 32 * p];
#pragma unroll
            for (int d = 0; d < 8; d++)
#pragma unroll
                for (int p = 0; p < 8; p++)
                    acc[d][p] = ffma2(q2[d], v2[p], acc[d][p]);
        }
    }
#pragma unroll
    for (int p = 0; p < 8; p++) {
        int e = 2 * tx + 32 * p;
        float t0 = g_t[b * D_ + e], t1 = g_t[b * D_ + e + 1];
#pragma unroll
        for (int d = 0; d < 8; d++) {
            float lo, hi; unpack2(acc[d][p], lo, hi);
            int n = n0 + ty * 8 + d;
            *(float2*)&out[((size_t)b * N_ + n) * D_ + e] = make_float2(lo + t0, hi + t1);
        }
    }
}

// ---------------- launch ----------------
extern "C" void kernel_launch(void* const* d_in, const int* in_sizes, int n_in,
                              void* d_out, int out_size) {
    const float* query = (const float*)d_in[0];
    const float* key   = (const float*)d_in[1];
    const float* value = (const float*)d_in[2];
    const void*  maskraw = d_in[3];
    // need_weights (index 4) may or may not be passed as an array
    int o = (n_in >= 11) ? 5 : 4;
    const float* Wq = (const float*)d_in[o + 0];
    const float* bq = (const float*)d_in[o + 1];
    const float* Wk = (const float*)d_in[o + 2];
    const float* bk = (const float*)d_in[o + 3];
    const float* Wv = (const float*)d_in[o + 4];
    const float* bv = (const float*)d_in[o + 5];
    float* out = (float*)d_out;
    (void)in_sizes; (void)out_size;

    k_detect<<<1, 256>>>((const unsigned char*)maskraw);
    k_maskconv<<<(B_ * N_ + 255) / 256, 256>>>(maskraw);
    k_zero<<<(B_ * D_ * D_ + 255) / 256, 256>>>();
    k1_reduce<<<dim3(KCH, 2, B_), 256>>>(key, value);
    k_uw<<<B_, 256>>>(Wk, Wv);
    k2_T1<<<dim3(16, B_), 256>>>(Wk);
    k3_A<<<dim3(16, B_), 256>>>(Wv, bk, bv);
    k4_softmax<<<dim3(32, B_), 256>>>(bq);
    k5_M<<<dim3(16, B_), 256>>>(Wq);
    k6_out<<<dim3(64, B_), 256>>>(query, out);
}

// round 6
// speedup vs baseline: 1.4483x; 1.4483x over previous
#include <cuda_runtime.h>
#include <cuda_bf16.h>
#include <cstdint>
#include <cstddef>

#define B_ 8
#define N_ 8192
#define D_ 256

typedef unsigned long long ull;
typedef unsigned int u32;

// tcgen05 is an arch-SPECIFIC feature: legal only in the sm_103a/sm_100a
// compilation stages. The harness also builds a baseline compute_103 PTX
// stage where these instructions are rejected by ptxas — gate on the
// arch-feature macros and provide a correct FFMA fallback for that stage.
#if !defined(__CUDA_ARCH__) || defined(__CUDA_ARCH_FEAT_SM103_ALL) || defined(__CUDA_ARCH_FEAT_SM100_ALL) || defined(__CUDA_ARCH_FEAT_SM101_ALL)
#define TCOK 1
#else
#define TCOK 0
#endif

// ---------------- device scratch (no allocations allowed) ----------------
__device__ __nv_bfloat16 g_KTH[B_ * D_ * N_];   // key^T masked, hi  [b][d][n]
__device__ __nv_bfloat16 g_KTL[B_ * D_ * N_];   // key^T masked, lo
__device__ __nv_bfloat16 g_VTH[B_ * D_ * N_];   // value^T, hi       [b][e][n]
__device__ __nv_bfloat16 g_VTL[B_ * D_ * N_];
__device__ __nv_bfloat16 g_QH[B_ * N_ * D_];    // query hi          [b][n][d]
__device__ __nv_bfloat16 g_QL[B_ * N_ * D_];
__device__ __nv_bfloat16 g_MTH[B_ * D_ * D_];   // (Wq^T aw)^T hi    [b][e][i]
__device__ __nv_bfloat16 g_MTL[B_ * D_ * D_];
__device__ float g_S[B_ * D_ * D_];    // S[b] = key_m^T @ value
__device__ float g_T1[B_ * D_ * D_];   // Wk @ S
__device__ float g_A[B_ * D_ * D_];    // logits -> softmax (aw)
__device__ float g_rk[B_ * D_];
__device__ float g_rv[B_ * D_];
__device__ float g_u[B_ * D_];
__device__ float g_w[B_ * D_];
__device__ float g_t[B_ * D_];
__device__ float g_cm[B_];
__device__ int   g_kind;
__device__ float g_m[B_ * N_];

// ---------------- f32x2 helpers for the middle FFMA kernels ----------------
__device__ __forceinline__ ull pack2(float lo, float hi) {
    ull r; asm("mov.b64 %0, {%1,%2};" : "=l"(r) : "f"(lo), "f"(hi)); return r;
}
__device__ __forceinline__ void unpack2(ull v, float& lo, float& hi) {
    asm("mov.b64 {%0,%1}, %2;" : "=f"(lo), "=f"(hi) : "l"(v));
}
__device__ __forceinline__ ull ffma2(ull a, ull b, ull c) {
    ull d; asm("fma.rn.f32x2 %0, %1, %2, %3;" : "=l"(d) : "l"(a), "l"(b), "l"(c)); return d;
}

// ---------------- tcgen05 helpers (guarded) ----------------
#if TCOK
__device__ __forceinline__ u32 smem_u32(const void* p) {
    u32 a; asm("{ .reg .u64 t; cvta.to.shared.u64 t, %1; cvt.u32.u64 %0, t; }" : "=r"(a) : "l"(p));
    return a;
}
__device__ __forceinline__ int elect1() {
    u32 p;
    asm volatile("{\n\t.reg .pred p;\n\telect.sync _|p, 0xFFFFFFFF;\n\tselp.b32 %0, 1, 0, p;\n\t}" : "=r"(p));
    return (int)p;
}
__device__ __forceinline__ void mbar_init(u32 mbar, u32 cnt) {
    asm volatile("mbarrier.init.shared.b64 [%0], %1;" :: "r"(mbar), "r"(cnt) : "memory");
}
__device__ __forceinline__ void mbar_inval(u32 mbar) {
    asm volatile("mbarrier.inval.shared.b64 [%0];" :: "r"(mbar) : "memory");
}
__device__ __forceinline__ void mbar_wait(u32 mbar, u32 parity) {
    asm volatile(
        "{\n\t.reg .pred P;\n\t"
        "WL_%=:\n\t"
        "mbarrier.try_wait.parity.acquire.cta.shared::cta.b64 P, [%0], %1, 0x989680;\n\t"
        "@P bra WD_%=;\n\t"
        "bra.uni WL_%=;\n\t"
        "WD_%=:\n\t}"
        :: "r"(mbar), "r"(parity) : "memory");
}
__device__ __forceinline__ void tmem_alloc(u32 smem_dst, u32 ncols) {
    asm volatile("tcgen05.alloc.cta_group::1.sync.aligned.shared::cta.b32 [%0], %1;"
                 :: "r"(smem_dst), "r"(ncols) : "memory");
}
__device__ __forceinline__ void tmem_dealloc(u32 tmem, u32 ncols) {
    asm volatile("tcgen05.dealloc.cta_group::1.sync.aligned.b32 %0, %1;" :: "r"(tmem), "r"(ncols));
}
__device__ __forceinline__ void mma_f16_ss(u32 d_tmem, ull a_desc, ull b_desc, u32 idesc, int accum) {
    u32 z = 0;
    asm volatile(
        "{\n\t.reg .pred p;\n\tsetp.ne.u32 p, %5, 0;\n\t"
        "tcgen05.mma.cta_group::1.kind::f16 [%0], %1, %2, %3, {%4, %4, %4, %4}, p;\n\t}"
        :: "r"(d_tmem), "l"(a_desc), "l"(b_desc), "r"(idesc), "r"(z), "r"((u32)accum) : "memory");
}
__device__ __forceinline__ void mma_commit(u32 mbar) {
    asm volatile("tcgen05.commit.cta_group::1.mbarrier::arrive::one.shared::cluster.b64 [%0];"
                 :: "r"(mbar) : "memory");
}
__device__ __forceinline__ void fence_async_proxy() {
    asm volatile("fence.proxy.async.shared::cta;" ::: "memory");
}
__device__ __forceinline__ void tc_fence_after() {
    asm volatile("tcgen05.fence::after_thread_sync;" ::: "memory");
}
__device__ __forceinline__ void tmem_wait_ld() {
    asm volatile("tcgen05.wait::ld.sync.aligned;" ::: "memory");
}

#define LDTM32(r, addr)                                                      \
    asm volatile("tcgen05.ld.sync.aligned.32x32b.x32.b32 "                   \
        "{%0, %1, %2, %3, %4, %5, %6, %7, %8, %9, %10, %11, %12, %13, %14, %15, " \
        " %16, %17, %18, %19, %20, %21, %22, %23, %24, %25, %26, %27, %28, %29, %30, %31}, [%32];" \
        : "=r"((r)[0]), "=r"((r)[1]), "=r"((r)[2]), "=r"((r)[3]),            \
          "=r"((r)[4]), "=r"((r)[5]), "=r"((r)[6]), "=r"((r)[7]),            \
          "=r"((r)[8]), "=r"((r)[9]), "=r"((r)[10]), "=r"((r)[11]),          \
          "=r"((r)[12]), "=r"((r)[13]), "=r"((r)[14]), "=r"((r)[15]),        \
          "=r"((r)[16]), "=r"((r)[17]), "=r"((r)[18]), "=r"((r)[19]),        \
          "=r"((r)[20]), "=r"((r)[21]), "=r"((r)[22]), "=r"((r)[23]),        \
          "=r"((r)[24]), "=r"((r)[25]), "=r"((r)[26]), "=r"((r)[27]),        \
          "=r"((r)[28]), "=r"((r)[29]), "=r"((r)[30]), "=r"((r)[31])         \
        : "r"(addr))

__device__ __forceinline__ u32 sw128(u32 off) { return off ^ ((off >> 3) & 0x70); }

// SW128 K-major descriptor base (version=1, SBO=64, LBO=1, layout=2)
#define DESC_BASE ((2ull << 61) | (1ull << 46) | (64ull << 32) | (1ull << 16))
__device__ __forceinline__ ull mk_desc(u32 addr) { return DESC_BASE | ((ull)(addr >> 4) & 0x3FFF); }

// idesc: F32 accum, BF16 x BF16, M=128, N=256
#define MMA_IDESC 0x8400490u
#endif  // TCOK

// smem layout for both MMA kernels (bytes)
#define SM_TPTR 0
#define SM_MBAR 8
#define SM_AH 1024
#define SM_AL (1024 + 16384)
#define SM_BH (1024 + 32768)
#define SM_BL (1024 + 65536)
#define SMEM_TOTAL (1024 + 98304)

// ---------------- mask detect + canonicalize (+cm) ----------------
__global__ void k_detect(const unsigned char* __restrict__ raw) {
    __shared__ int s1;
    if (threadIdx.x == 0) s1 = 0;
    __syncthreads();
    int local = 0;
    for (int i = threadIdx.x; i < 65536; i += blockDim.x)
        if ((i & 3) == 1 && raw[i] != 0) local = 1;
    if (local) atomicOr(&s1, 1);
    __syncthreads();
    if (threadIdx.x == 0) g_kind = s1 ? 0 : 1;
}

__global__ void k_maskconv(const void* __restrict__ rawv) {
    int n = blockIdx.x * blockDim.x + threadIdx.x;
    bool padded;
    if (g_kind == 0) padded = ((const unsigned char*)rawv)[n] != 0;
    else             padded = ((const unsigned int*)rawv)[n] != 0u;
    float m = padded ? 0.f : 1.f;
    g_m[n] = m;
    float s = m;
#pragma unroll
    for (int o = 16; o > 0; o >>= 1) s += __shfl_xor_sync(0xffffffffu, s, o);
    __shared__ float red[8];
    int wid = threadIdx.x >> 5, lane = threadIdx.x & 31;
    if (lane == 0) red[wid] = s;
    __syncthreads();
    if (threadIdx.x == 0) {
        float t = 0.f;
        for (int i = 0; i < 8; i++) t += red[i];
        atomicAdd(&g_cm[n >> 13], t);
    }
}

__global__ void k_zero() {
    int i = blockIdx.x * blockDim.x + threadIdx.x;
    if (i < B_ * D_ * D_) g_S[i] = 0.f;
    if (i < B_ * D_) { g_rk[i] = 0.f; g_rv[i] = 0.f; }
    if (i < B_) g_cm[i] = 0.f;
}

// ---------------- query -> bf16 hi/lo (elementwise) ----------------
__global__ void c_q(const float4* __restrict__ q4) {
    size_t i = (size_t)blockIdx.x * blockDim.x + threadIdx.x;  // < 4194304
    float4 x = q4[i];
    __nv_bfloat16 h0 = __float2bfloat16(x.x), h1 = __float2bfloat16(x.y);
    __nv_bfloat16 h2 = __float2bfloat16(x.z), h3 = __float2bfloat16(x.w);
    float l0 = x.x - __bfloat162float(h0), l1 = x.y - __bfloat162float(h1);
    float l2 = x.z - __bfloat162float(h2), l3 = x.w - __bfloat162float(h3);
    uint2 hv, lv;
    hv.x = (u32)__bfloat16_as_ushort(h0) | ((u32)__bfloat16_as_ushort(h1) << 16);
    hv.y = (u32)__bfloat16_as_ushort(h2) | ((u32)__bfloat16_as_ushort(h3) << 16);
    lv.x = (u32)__bfloat16_as_ushort(__float2bfloat16(l0)) | ((u32)__bfloat16_as_ushort(__float2bfloat16(l1)) << 16);
    lv.y = (u32)__bfloat16_as_ushort(__float2bfloat16(l2)) | ((u32)__bfloat16_as_ushort(__float2bfloat16(l3)) << 16);
    ((uint2*)g_QH)[i] = hv;
    ((uint2*)g_QL)[i] = lv;
}

// ---------------- key/value -> transposed bf16 hi/lo (+ masked column sums) ----
__global__ void __launch_bounds__(256)
c_kvt(const float* __restrict__ src, __nv_bfloat16* __restrict__ dh,
      __nv_bfloat16* __restrict__ dl, float* __restrict__ rsum, int maskData) {
    __shared__ float st[64][68];
    __shared__ float smv[64];
    const int b = blockIdx.z, d0 = blockIdx.y * 64, n0 = blockIdx.x * 64;
    const int tid = threadIdx.x;
#pragma unroll
    for (int i = tid; i < 1024; i += 256) {
        int r = i >> 4, c4 = i & 15;
        float4 v = *(const float4*)(src + ((size_t)b * N_ + n0 + r) * D_ + d0 + c4 * 4);
        *(float4*)&st[r][c4 * 4] = v;
        if (c4 == 0) smv[r] = g_m[(size_t)b * N_ + n0 + r];
    }
    __syncthreads();
#pragma unroll
    for (int w = tid; w < 2048; w += 256) {
        int rd = w >> 5, c2 = w & 31;
        int n = c2 * 2;
        float x0 = st[n][rd], x1 = st[n + 1][rd];
        if (maskData) { x0 *= smv[n]; x1 *= smv[n + 1]; }
        __nv_bfloat16 h0 = __float2bfloat16(x0), h1 = __float2bfloat16(x1);
        float l0 = x0 - __bfloat162float(h0), l1 = x1 - __bfloat162float(h1);
        size_t o = ((size_t)b * D_ + d0 + rd) * N_ + n0 + n;
        *(u32*)(dh + o) = (u32)__bfloat16_as_ushort(h0) | ((u32)__bfloat16_as_ushort(h1) << 16);
        *(u32*)(dl + o) = (u32)__bfloat16_as_ushort(__float2bfloat16(l0)) |
                          ((u32)__bfloat16_as_ushort(__float2bfloat16(l1)) << 16);
    }
    if (tid < 64) {
        float s = 0.f;
#pragma unroll
        for (int n = 0; n < 64; n++) s += smv[n] * st[n][tid];
        atomicAdd(&rsum[b * D_ + d0 + tid], s);
    }
}

// ---------------- k1: S[b] += KT_slab @ VT^T via tcgen05 (split-K, bf16 hi/lo) ----
__global__ void __launch_bounds__(512, 1) k1_mma() {
#if TCOK
    extern __shared__ char smem[];
    const u32 sb = smem_u32(smem);
    const int tid = threadIdx.x, wid = tid >> 5, lid = tid & 31;
    const int b = blockIdx.z, d0 = blockIdx.y * 128, chunk = blockIdx.x;
    const int n_start = chunk * 512;

    if (wid == 0) tmem_alloc(sb + SM_TPTR, 256);
    if (tid == 0) mbar_init(sb + SM_MBAR, 1);
    __syncthreads();
    u32 tbase;
    asm volatile("ld.shared.b32 %0, [%1];" : "=r"(tbase) : "r"(sb + SM_TPTR));

    const ull dAH = mk_desc(sb + SM_AH), dAL = mk_desc(sb + SM_AL);
    const ull dBH = mk_desc(sb + SM_BH), dBL = mk_desc(sb + SM_BL);
    const size_t abase0 = ((size_t)b * D_ + d0) * N_;
    const size_t bbase0 = (size_t)b * D_ * N_;

    for (int c = 0; c < 8; c++) {
        if (c >= 1) mbar_wait(sb + SM_MBAR, (u32)((c - 1) & 1));
        const int n = n_start + c * 64;
#pragma unroll
        for (int i = tid; i < 1024; i += 512) {           // A: 128 rows x 64 bf16
            int r = i >> 3, c16 = i & 7;
            size_t off = abase0 + (size_t)r * N_ + n + c16 * 8;
            u32 sw = sw128((u32)(r * 128 + c16 * 16));
            *(uint4*)(smem + SM_AH + sw) = *(const uint4*)(g_KTH + off);
            *(uint4*)(smem + SM_AL + sw) = *(const uint4*)(g_KTL + off);
        }
#pragma unroll
        for (int i = tid; i < 2048; i += 512) {           // B: 256 rows x 64 bf16
            int r = i >> 3, c16 = i & 7;
            size_t off = bbase0 + (size_t)r * N_ + n + c16 * 8;
            u32 sw = sw128((u32)(r * 128 + c16 * 16));
            *(uint4*)(smem + SM_BH + sw) = *(const uint4*)(g_VTH + off);
            *(uint4*)(smem + SM_BL + sw) = *(const uint4*)(g_VTL + off);
        }
        __syncthreads();
        fence_async_proxy();
        if (wid == 0 && elect1()) {
#pragma unroll
            for (int ks = 0; ks < 4; ks++) {
                ull o = (ull)(ks * 2);
                mma_f16_ss(tbase, dAH + o, dBH + o, MMA_IDESC, !(c == 0 && ks == 0));
                mma_f16_ss(tbase, dAH + o, dBL + o, MMA_IDESC, 1);
                mma_f16_ss(tbase, dAL + o, dBH + o, MMA_IDESC, 1);
            }
            mma_commit(sb + SM_MBAR);
        }
        __syncthreads();
    }
    mbar_wait(sb + SM_MBAR, 1);   // chunk 7 completion: parity 7&1
    tc_fence_after();

    if (wid < 4) {
        float* dst0 = g_S + ((size_t)b * D_ + d0 + wid * 32 + lid) * D_;
#pragma unroll
        for (int blk = 0; blk < 8; blk++) {
            u32 r[32];
            LDTM32(r, tbase + blk * 32);
            tmem_wait_ld();
#pragma unroll
            for (int cc = 0; cc < 32; cc++)
                atomicAdd(dst0 + blk * 32 + cc, __uint_as_float(r[cc]));
        }
    }
    __syncthreads();
    if (tid == 0) mbar_inval(sb + SM_MBAR);
    __syncthreads();
    if (wid == 0) tmem_dealloc(tbase, 256);
#else
    // FFMA fallback (runs only if the non-'a' PTX stage is ever JIT-executed)
    const int tid = threadIdx.x;
    const int b = blockIdx.z, d0 = blockIdx.y * 128, chunk = blockIdx.x;
    const int n_start = chunk * 512;
    for (int idx = tid; idx < 128 * 256; idx += 512) {
        int d = d0 + (idx >> 8), e = idx & 255;
        const __nv_bfloat16* kh = g_KTH + ((size_t)b * D_ + d) * N_ + n_start;
        const __nv_bfloat16* kl = g_KTL + ((size_t)b * D_ + d) * N_ + n_start;
        const __nv_bfloat16* vh = g_VTH + ((size_t)b * D_ + e) * N_ + n_start;
        const __nv_bfloat16* vl = g_VTL + ((size_t)b * D_ + e) * N_ + n_start;
        float acc = 0.f;
        for (int n = 0; n < 512; n++) {
            float kx = __bfloat162float(kh[n]) + __bfloat162float(kl[n]);
            float vx = __bfloat162float(vh[n]) + __bfloat162float(vl[n]);
            acc += kx * vx;
        }
        atomicAdd(&g_S[((size_t)b * D_ + d) * D_ + e], acc);
    }
#endif
}

// ---------------- k_uw: u = Wk@rk, w = Wv@rv ----------------
__global__ void k_uw(const float* __restrict__ Wk, const float* __restrict__ Wv) {
    int b = blockIdx.x, d = threadIdx.x;
    float su = 0.f, sw = 0.f;
    for (int i = 0; i < D_; i++) {
        su += Wk[d * D_ + i] * g_rk[b * D_ + i];
        sw += Wv[d * D_ + i] * g_rv[b * D_ + i];
    }
    g_u[b * D_ + d] = su;
    g_w[b * D_ + d] = sw;
}

// ---------------- k2: T1 = Wk @ S ----------------
__global__ void __launch_bounds__(256, 1)
k2_T1(const float* __restrict__ Wk) {
    const int b = blockIdx.y, d0 = blockIdx.x * 16;
    const int tid = threadIdx.x, tx = tid & 15, ty = tid >> 4;
    __shared__ float sA[16][16];
    __shared__ float sB[16][256];
    ull acc[8];
#pragma unroll
    for (int p = 0; p < 8; p++) acc[p] = 0ull;
    const float* Sb = g_S + b * D_ * D_;
    for (int i0 = 0; i0 < D_; i0 += 16) {
        __syncthreads();
        if (tid < 64) {
            int r = tid >> 2, q = tid & 3;
            *(float4*)&sA[r][q * 4] = *(const float4*)(Wk + (size_t)(d0 + r) * D_ + i0 + q * 4);
        }
#pragma unroll
        for (int i = 0; i < 4; i++) {
            int idx = tid + 256 * i;
            int r = idx >> 6, q = idx & 63;
            *(float4*)&sB[r][q * 4] = *(const float4*)(Sb + (size_t)(i0 + r) * D_ + q * 4);
        }
        __syncthreads();
#pragma unroll
        for (int ii = 0; ii < 16; ii++) {
            float a = sA[ty][ii];
            ull a2 = pack2(a, a);
#pragma unroll
            for (int p = 0; p < 8; p++)
                acc[p] = ffma2(a2, *(const ull*)&sB[ii][2 * tx + 32 * p], acc[p]);
        }
    }
    float* T1b = g_T1 + b * D_ * D_;
    int row = d0 + ty;
#pragma unroll
    for (int p = 0; p < 8; p++) {
        float lo, hi; unpack2(acc[p], lo, hi);
        *(float2*)&T1b[row * D_ + 2 * tx + 32 * p] = make_float2(lo, hi);
    }
}

// ---------------- k3: A = (T1 @ Wv^T + rank-1) / sqrt(8) ----------------
__global__ void __launch_bounds__(256, 1)
k3_A(const float* __restrict__ Wv, const float* __restrict__ bk,
     const float* __restrict__ bv) {
    const int b = blockIdx.y, d0 = blockIdx.x * 16;
    const int tid = threadIdx.x, tx = tid & 15, ty = tid >> 4;
    __shared__ float sA[16][16];
    __shared__ float sB[16][258];
    ull acc[8];
#pragma unroll
    for (int p = 0; p < 8; p++) acc[p] = 0ull;
    const float* T1b = g_T1 + b * D_ * D_;
    for (int j0 = 0; j0 < D_; j0 += 16) {
        __syncthreads();
        if (tid < 64) {
            int r = tid >> 2, q = tid & 3;
            *(float4*)&sA[r][q * 4] = *(const float4*)(T1b + (size_t)(d0 + r) * D_ + j0 + q * 4);
        }
#pragma unroll
        for (int i = 0; i < 4; i++) {
            int idx = tid + 256 * i;
            int q = idx & 3, e = idx >> 2;
            float4 v = *(const float4*)(Wv + (size_t)e * D_ + j0 + q * 4);
            sB[q * 4 + 0][e] = v.x; sB[q * 4 + 1][e] = v.y;
            sB[q * 4 + 2][e] = v.z; sB[q * 4 + 3][e] = v.w;
        }
        __syncthreads();
#pragma unroll
        for (int jj = 0; jj < 16; jj++) {
            float a = sA[ty][jj];
            ull a2 = pack2(a, a);
#pragma unroll
            for (int p = 0; p < 8; p++)
                acc[p] = ffma2(a2, *(const ull*)&sB[jj][2 * tx + 32 * p], acc[p]);
        }
    }
    const int d = d0 + ty;
    const float u_d = g_u[b * D_ + d], bk_d = bk[d], cmv = g_cm[b];
    const float inv = 0.3535533905932738f;
    float* Ab = g_A + b * D_ * D_;
#pragma unroll
    for (int p = 0; p < 8; p++) {
        float lo, hi; unpack2(acc[p], lo, hi);
        int e = 2 * tx + 32 * p;
        float bv0 = bv[e], bv1 = bv[e + 1];
        float w0 = g_w[b * D_ + e], w1 = g_w[b * D_ + e + 1];
        lo = (lo + u_d * bv0 + bk_d * w0 + cmv * bk_d * bv0) * inv;
        hi = (hi + u_d * bv1 + bk_d * w1 + cmv * bk_d * bv1) * inv;
        *(float2*)&Ab[d * D_ + e] = make_float2(lo, hi);
    }
}

// ---------------- k4: column softmax + t = bq^T aw ----------------
__global__ void k4_softmax(const float* __restrict__ bq) {
    const int b = blockIdx.y;
    const int w = threadIdx.x >> 5, lane = threadIdx.x & 31;
    const int e = blockIdx.x * 8 + w;
    float* col = g_A + b * D_ * D_ + e;
    float v[8];
#pragma unroll
    for (int s = 0; s < 8; s++) v[s] = col[(lane + 32 * s) * D_];
    float mx = v[0];
#pragma unroll
    for (int s = 1; s < 8; s++) mx = fmaxf(mx, v[s]);
#pragma unroll
    for (int o = 16; o > 0; o >>= 1) mx = fmaxf(mx, __shfl_xor_sync(0xffffffffu, mx, o));
    float sum = 0.f;
#pragma unroll
    for (int s = 0; s < 8; s++) { v[s] = expf(v[s] - mx); sum += v[s]; }
#pragma unroll
    for (int o = 16; o > 0; o >>= 1) sum += __shfl_xor_sync(0xffffffffu, sum, o);
    const float isum = 1.f / sum;
    float tacc = 0.f;
#pragma unroll
    for (int s = 0; s < 8; s++) {
        float p = v[s] * isum;
        col[(lane + 32 * s) * D_] = p;
        tacc += p * bq[lane + 32 * s];
    }
#pragma unroll
    for (int o = 16; o > 0; o >>= 1) tacc += __shfl_xor_sync(0xffffffffu, tacc, o);
    if (lane == 0) g_t[b * D_ + e] = tacc;
}

// ---------------- k5: M^T[e][i] = sum_d Wq[d][i] aw[d][e] -> bf16 hi/lo ------
__global__ void __launch_bounds__(256, 1)
k5_M(const float* __restrict__ Wq) {
    const int b = blockIdx.y, i0 = blockIdx.x * 16;
    const int tid = threadIdx.x, tx = tid & 15, ty = tid >> 4;
    __shared__ float sA[16][17];
    __shared__ float sB[16][256];
    ull acc[8];
#pragma unroll
    for (int p = 0; p < 8; p++) acc[p] = 0ull;
    const float* awb = g_A + b * D_ * D_;
    for (int dd0 = 0; dd0 < D_; dd0 += 16) {
        __syncthreads();
        if (tid < 64) {
            int r = tid >> 2, q = tid & 3;
            float4 v = *(const float4*)(Wq + (size_t)(dd0 + r) * D_ + i0 + q * 4);
            sA[q * 4 + 0][r] = v.x; sA[q * 4 + 1][r] = v.y;
            sA[q * 4 + 2][r] = v.z; sA[q * 4 + 3][r] = v.w;
        }
#pragma unroll
        for (int i = 0; i < 4; i++) {
            int idx = tid + 256 * i;
            int r = idx >> 6, q = idx & 63;
            *(float4*)&sB[r][q * 4] = *(const float4*)(awb + (size_t)(dd0 + r) * D_ + q * 4);
        }
        __syncthreads();
#pragma unroll
        for (int dd = 0; dd < 16; dd++) {
            float a = sA[ty][dd];
            ull a2 = pack2(a, a);
#pragma unroll
            for (int p = 0; p < 8; p++)
                acc[p] = ffma2(a2, *(const ull*)&sB[dd][2 * tx + 32 * p], acc[p]);
        }
    }
    const int row = i0 + ty;
#pragma unroll
    for (int p = 0; p < 8; p++) {
        float lo, hi; unpack2(acc[p], lo, hi);
        int e0 = 2 * tx + 32 * p, e1 = e0 + 1;
        __nv_bfloat16 h0 = __float2bfloat16(lo);
        __nv_bfloat16 h1 = __float2bfloat16(hi);
        g_MTH[((size_t)b * D_ + e0) * D_ + row] = h0;
        g_MTL[((size_t)b * D_ + e0) * D_ + row] = __float2bfloat16(lo - __bfloat162float(h0));
        g_MTH[((size_t)b * D_ + e1) * D_ + row] = h1;
        g_MTL[((size_t)b * D_ + e1) * D_ + row] = __float2bfloat16(hi - __bfloat162float(h1));
    }
}

// ---------------- k6: out = query @ M + t via tcgen05 (bf16 hi/lo) -----------
__global__ void __launch_bounds__(512, 1) k6_mma(float* __restrict__ out) {
#if TCOK
    extern __shared__ char smem[];
    const u32 sb = smem_u32(smem);
    const int tid = threadIdx.x, wid = tid >> 5, lid = tid & 31;
    const int b = blockIdx.y, n0 = blockIdx.x * 128;

    if (wid == 0) tmem_alloc(sb + SM_TPTR, 256);
    if (tid == 0) mbar_init(sb + SM_MBAR, 1);
    __syncthreads();
    u32 tbase;
    asm volatile("ld.shared.b32 %0, [%1];" : "=r"(tbase) : "r"(sb + SM_TPTR));

    const ull dAH = mk_desc(sb + SM_AH), dAL = mk_desc(sb + SM_AL);
    const ull dBH = mk_desc(sb + SM_BH), dBL = mk_desc(sb + SM_BL);
    const size_t abase0 = ((size_t)b * N_ + n0) * D_;
    const size_t bbase0 = (size_t)b * D_ * D_;

    for (int c = 0; c < 4; c++) {
        if (c >= 1) mbar_wait(sb + SM_MBAR, (u32)((c - 1) & 1));
        const int dc = c * 64;
#pragma unroll
        for (int i = tid; i < 1024; i += 512) {           // A: q rows
            int r = i >> 3, c16 = i & 7;
            size_t off = abase0 + (size_t)r * D_ + dc + c16 * 8;
            u32 sw = sw128((u32)(r * 128 + c16 * 16));
            *(uint4*)(smem + SM_AH + sw) = *(const uint4*)(g_QH + off);
            *(uint4*)(smem + SM_AL + sw) = *(const uint4*)(g_QL + off);
        }
#pragma unroll
        for (int i = tid; i < 2048; i += 512) {           // B: M^T rows
            int r = i >> 3, c16 = i & 7;
            size_t off = bbase0 + (size_t)r * D_ + dc + c16 * 8;
            u32 sw = sw128((u32)(r * 128 + c16 * 16));
            *(uint4*)(smem + SM_BH + sw) = *(const uint4*)(g_MTH + off);
            *(uint4*)(smem + SM_BL + sw) = *(const uint4*)(g_MTL + off);
        }
        __syncthreads();
        fence_async_proxy();
        if (wid == 0 && elect1()) {
#pragma unroll
            for (int ks = 0; ks < 4; ks++) {
                ull o = (ull)(ks * 2);
                mma_f16_ss(tbase, dAH + o, dBH + o, MMA_IDESC, !(c == 0 && ks == 0));
                mma_f16_ss(tbase, dAH + o, dBL + o, MMA_IDESC, 1);
                mma_f16_ss(tbase, dAL + o, dBH + o, MMA_IDESC, 1);
            }
            mma_commit(sb + SM_MBAR);
        }
        __syncthreads();
    }
    mbar_wait(sb + SM_MBAR, 1);    // chunk 3 completion: parity 3&1
    tc_fence_after();

    float* stage = (float*)(smem + 1024);   // [128][68]
    for (int cb = 0; cb < 4; cb++) {
        __syncthreads();
        if (wid < 4) {
            u32 r0[32], r1[32];
            LDTM32(r0, tbase + cb * 64);
            LDTM32(r1, tbase + cb * 64 + 32);
            tmem_wait_ld();
            float* srow = stage + (wid * 32 + lid) * 68;
#pragma unroll
            for (int cc = 0; cc < 32; cc++) {
                srow[cc] = __uint_as_float(r0[cc]);
                srow[32 + cc] = __uint_as_float(r1[cc]);
            }
        }
        __syncthreads();
#pragma unroll
        for (int i = tid; i < 2048; i += 512) {
            int r = i >> 4, c4 = i & 15;
            float4 v = *(float4*)(stage + r * 68 + c4 * 4);
            int e = cb * 64 + c4 * 4;
            v.x += g_t[b * D_ + e];
            v.y += g_t[b * D_ + e + 1];
            v.z += g_t[b * D_ + e + 2];
            v.w += g_t[b * D_ + e + 3];
            *(float4*)(out + ((size_t)b * N_ + n0 + r) * D_ + e) = v;
        }
    }
    __syncthreads();
    if (tid == 0) mbar_inval(sb + SM_MBAR);
    __syncthreads();
    if (wid == 0) tmem_dealloc(tbase, 256);
#else
    // FFMA fallback
    const int tid = threadIdx.x;
    const int b = blockIdx.y, n0 = blockIdx.x * 128;
    for (int idx = tid; idx < 128 * 256; idx += 512) {
        int n = n0 + (idx >> 8), e = idx & 255;
        const __nv_bfloat16* qh = g_QH + ((size_t)b * N_ + n) * D_;
        const __nv_bfloat16* ql = g_QL + ((size_t)b * N_ + n) * D_;
        const __nv_bfloat16* mh = g_MTH + ((size_t)b * D_ + e) * D_;
        const __nv_bfloat16* ml = g_MTL + ((size_t)b * D_ + e) * D_;
        float acc = g_t[b * D_ + e];
        for (int d = 0; d < D_; d++) {
            float qx = __bfloat162float(qh[d]) + __bfloat162float(ql[d]);
            float mx = __bfloat162float(mh[d]) + __bfloat162float(ml[d]);
            acc += qx * mx;
        }
        out[((size_t)b * N_ + n) * D_ + e] = acc;
    }
#endif
}

// ---------------- launch ----------------
extern "C" void kernel_launch(void* const* d_in, const int* in_sizes, int n_in,
                              void* d_out, int out_size) {
    const float* query = (const float*)d_in[0];
    const float* key   = (const float*)d_in[1];
    const float* value = (const float*)d_in[2];
    const void*  maskraw = d_in[3];
    int o = (n_in >= 11) ? 5 : 4;
    const float* Wq = (const float*)d_in[o + 0];
    const float* bq = (const float*)d_in[o + 1];
    const float* Wk = (const float*)d_in[o + 2];
    const float* bk = (const float*)d_in[o + 3];
    const float* Wv = (const float*)d_in[o + 4];
    const float* bv = (const float*)d_in[o + 5];
    float* out = (float*)d_out;
    (void)in_sizes; (void)out_size;

    cudaFuncSetAttribute(k1_mma, cudaFuncAttributeMaxDynamicSharedMemorySize, SMEM_TOTAL);
    cudaFuncSetAttribute(k6_mma, cudaFuncAttributeMaxDynamicSharedMemorySize, SMEM_TOTAL);

    __nv_bfloat16 *KTH, *KTL, *VTH, *VTL;
    cudaGetSymbolAddress((void**)&KTH, g_KTH);
    cudaGetSymbolAddress((void**)&KTL, g_KTL);
    cudaGetSymbolAddress((void**)&VTH, g_VTH);
    cudaGetSymbolAddress((void**)&VTL, g_VTL);
    float *rk, *rv;
    cudaGetSymbolAddress((void**)&rk, g_rk);
    cudaGetSymbolAddress((void**)&rv, g_rv);

    k_zero<<<(B_ * D_ * D_ + 255) / 256, 256>>>();
    k_detect<<<1, 256>>>((const unsigned char*)maskraw);
    k_maskconv<<<(B_ * N_) / 256, 256>>>(maskraw);
    c_q<<<(B_ * N_ * D_ / 4) / 256, 256>>>((const float4*)query);
    c_kvt<<<dim3(N_ / 64, D_ / 64, B_), 256>>>(key, KTH, KTL, rk, 1);
    c_kvt<<<dim3(N_ / 64, D_ / 64, B_), 256>>>(value, VTH, VTL, rv, 0);
    k1_mma<<<dim3(16, 2, B_), 512, SMEM_TOTAL>>>();
    k_uw<<<B_, 256>>>(Wk, Wv);
    k2_T1<<<dim3(16, B_), 256>>>(Wk);
    k3_A<<<dim3(16, B_), 256>>>(Wv, bk, bv);
    k4_softmax<<<dim3(32, B_), 256>>>(bq);
    k5_M<<<dim3(16, B_), 256>>>(Wq);
    k6_mma<<<dim3(64, B_), 512, SMEM_TOTAL>>>(out);
}

// round 7
// speedup vs baseline: 1.8151x; 1.2533x over previous
#include <cuda_runtime.h>
#include <cuda_bf16.h>
#include <cstdint>
#include <cstddef>

#define B_ 8
#define N_ 8192
#define D_ 256

typedef unsigned long long ull;
typedef unsigned int u32;

// tcgen05 is arch-specific (sm_103a). The harness also builds a baseline
// compute_103 stage where tcgen05 is illegal -> gate + FFMA fallback.
#if !defined(__CUDA_ARCH__) || defined(__CUDA_ARCH_FEAT_SM103_ALL) || defined(__CUDA_ARCH_FEAT_SM100_ALL) || defined(__CUDA_ARCH_FEAT_SM101_ALL)
#define TCOK 1
#else
#define TCOK 0
#endif

// ---------------- device scratch ----------------
__device__ __nv_bfloat16 g_MTH[B_ * D_ * D_];   // (Wq^T aw)^T hi [b][e][i]
__device__ __nv_bfloat16 g_MTL[B_ * D_ * D_];
__device__ float g_S[B_ * D_ * D_];
__device__ float g_T1[B_ * D_ * D_];
__device__ float g_A[B_ * D_ * D_];
__device__ float g_rk[B_ * D_];
__device__ float g_rv[B_ * D_];
__device__ float g_u[B_ * D_];
__device__ float g_w[B_ * D_];
__device__ float g_t[B_ * D_];
__device__ float g_cm[B_];
__device__ int   g_kind;
__device__ float g_m[B_ * N_];

// ---------------- f32x2 helpers ----------------
__device__ __forceinline__ ull pack2(float lo, float hi) {
    ull r; asm("mov.b64 %0, {%1,%2};" : "=l"(r) : "f"(lo), "f"(hi)); return r;
}
__device__ __forceinline__ void unpack2(ull v, float& lo, float& hi) {
    asm("mov.b64 {%0,%1}, %2;" : "=f"(lo), "=f"(hi) : "l"(v));
}
__device__ __forceinline__ ull ffma2(ull a, ull b, ull c) {
    ull d; asm("fma.rn.f32x2 %0, %1, %2, %3;" : "=l"(d) : "l"(a), "l"(b), "l"(c)); return d;
}

// split f32 pair -> bf16x2 hi + bf16x2 lo (elem0 in low half)
__device__ __forceinline__ void cvt2(float x0, float x1, u32& h2, u32& l2) {
    asm("cvt.rn.bf16x2.f32 %0, %1, %2;" : "=r"(h2) : "f"(x1), "f"(x0));
    float hf0 = __uint_as_float(h2 << 16);
    float hf1 = __uint_as_float(h2 & 0xFFFF0000u);
    float d0 = x0 - hf0, d1 = x1 - hf1;
    asm("cvt.rn.bf16x2.f32 %0, %1, %2;" : "=r"(l2) : "f"(d1), "f"(d0));
}

// ---------------- tcgen05 helpers (guarded) ----------------
#if TCOK
__device__ __forceinline__ u32 smem_u32(const void* p) {
    u32 a; asm("{ .reg .u64 t; cvta.to.shared.u64 t, %1; cvt.u32.u64 %0, t; }" : "=r"(a) : "l"(p));
    return a;
}
__device__ __forceinline__ int elect1() {
    u32 p;
    asm volatile("{\n\t.reg .pred p;\n\telect.sync _|p, 0xFFFFFFFF;\n\tselp.b32 %0, 1, 0, p;\n\t}" : "=r"(p));
    return (int)p;
}
__device__ __forceinline__ void mbar_init(u32 mbar, u32 cnt) {
    asm volatile("mbarrier.init.shared.b64 [%0], %1;" :: "r"(mbar), "r"(cnt) : "memory");
}
__device__ __forceinline__ void mbar_inval(u32 mbar) {
    asm volatile("mbarrier.inval.shared.b64 [%0];" :: "r"(mbar) : "memory");
}
__device__ __forceinline__ void mbar_wait(u32 mbar, u32 parity) {
    asm volatile(
        "{\n\t.reg .pred P;\n\t"
        "WL_%=:\n\t"
        "mbarrier.try_wait.parity.acquire.cta.shared::cta.b64 P, [%0], %1, 0x989680;\n\t"
        "@P bra WD_%=;\n\t"
        "bra.uni WL_%=;\n\t"
        "WD_%=:\n\t}"
        :: "r"(mbar), "r"(parity) : "memory");
}
__device__ __forceinline__ void tmem_alloc(u32 smem_dst, u32 ncols) {
    asm volatile("tcgen05.alloc.cta_group::1.sync.aligned.shared::cta.b32 [%0], %1;"
                 :: "r"(smem_dst), "r"(ncols) : "memory");
}
__device__ __forceinline__ void tmem_dealloc(u32 tmem, u32 ncols) {
    asm volatile("tcgen05.dealloc.cta_group::1.sync.aligned.b32 %0, %1;" :: "r"(tmem), "r"(ncols));
}
__device__ __forceinline__ void mma_f16_ss(u32 d_tmem, ull a_desc, ull b_desc, u32 idesc, int accum) {
    u32 z = 0;
    asm volatile(
        "{\n\t.reg .pred p;\n\tsetp.ne.u32 p, %5, 0;\n\t"
        "tcgen05.mma.cta_group::1.kind::f16 [%0], %1, %2, %3, {%4, %4, %4, %4}, p;\n\t}"
        :: "r"(d_tmem), "l"(a_desc), "l"(b_desc), "r"(idesc), "r"(z), "r"((u32)accum) : "memory");
}
__device__ __forceinline__ void mma_commit(u32 mbar) {
    asm volatile("tcgen05.commit.cta_group::1.mbarrier::arrive::one.shared::cluster.b64 [%0];"
                 :: "r"(mbar) : "memory");
}
__device__ __forceinline__ void fence_async_proxy() {
    asm volatile("fence.proxy.async.shared::cta;" ::: "memory");
}
__device__ __forceinline__ void tc_fence_after() {
    asm volatile("tcgen05.fence::after_thread_sync;" ::: "memory");
}
__device__ __forceinline__ void tmem_wait_ld() {
    asm volatile("tcgen05.wait::ld.sync.aligned;" ::: "memory");
}

#define LDTM32(r, addr)                                                      \
    asm volatile("tcgen05.ld.sync.aligned.32x32b.x32.b32 "                   \
        "{%0, %1, %2, %3, %4, %5, %6, %7, %8, %9, %10, %11, %12, %13, %14, %15, " \
        " %16, %17, %18, %19, %20, %21, %22, %23, %24, %25, %26, %27, %28, %29, %30, %31}, [%32];" \
        : "=r"((r)[0]), "=r"((r)[1]), "=r"((r)[2]), "=r"((r)[3]),            \
          "=r"((r)[4]), "=r"((r)[5]), "=r"((r)[6]), "=r"((r)[7]),            \
          "=r"((r)[8]), "=r"((r)[9]), "=r"((r)[10]), "=r"((r)[11]),          \
          "=r"((r)[12]), "=r"((r)[13]), "=r"((r)[14]), "=r"((r)[15]),        \
          "=r"((r)[16]), "=r"((r)[17]), "=r"((r)[18]), "=r"((r)[19]),        \
          "=r"((r)[20]), "=r"((r)[21]), "=r"((r)[22]), "=r"((r)[23]),        \
          "=r"((r)[24]), "=r"((r)[25]), "=r"((r)[26]), "=r"((r)[27]),        \
          "=r"((r)[28]), "=r"((r)[29]), "=r"((r)[30]), "=r"((r)[31])         \
        : "r"(addr))

__device__ __forceinline__ u32 sw128(u32 off) { return off ^ ((off >> 3) & 0x70); }

#define DESC_BASE ((2ull << 61) | (1ull << 46) | (64ull << 32) | (1ull << 16))
__device__ __forceinline__ ull mk_desc(u32 addr) { return DESC_BASE | ((ull)(addr >> 4) & 0x3FFF); }

// idesc: F32 accum, BF16 x BF16, M=128, N=256
#define MMA_IDESC 0x8400490u
#endif  // TCOK

// k6 smem layout
#define SM_TPTR 0
#define SM_MBAR 8
#define SM_AH 1024
#define SM_AL (1024 + 16384)
#define SM_BH (1024 + 32768)
#define SM_BL (1024 + 65536)
#define SMEM_TOTAL (1024 + 98304)

// k1 smem layout (fp32 staging + MMA operand bufs)
#define K1_SMV  256                       // 64 floats mask
#define K1_STGK 1024                      // 64 x 132 f32 = 33792B
#define K1_STGV 34816                     // 64 x 260 f32 = 66560B
#define K1_AH   101376
#define K1_AL   (101376 + 16384)
#define K1_BH   (101376 + 32768)
#define K1_BL   (101376 + 65536)
#define K1_TOTAL (101376 + 98304)         // 199680 B

// ---------------- mask detect + canonicalize (+cm) ----------------
__global__ void k_detect(const unsigned char* __restrict__ raw) {
    __shared__ int s1;
    if (threadIdx.x == 0) s1 = 0;
    __syncthreads();
    int local = 0;
    for (int i = threadIdx.x; i < 65536; i += blockDim.x)
        if ((i & 3) == 1 && raw[i] != 0) local = 1;
    if (local) atomicOr(&s1, 1);
    __syncthreads();
    if (threadIdx.x == 0) g_kind = s1 ? 0 : 1;
}

__global__ void k_maskconv(const void* __restrict__ rawv) {
    int n = blockIdx.x * blockDim.x + threadIdx.x;
    bool padded;
    if (g_kind == 0) padded = ((const unsigned char*)rawv)[n] != 0;
    else             padded = ((const unsigned int*)rawv)[n] != 0u;
    float m = padded ? 0.f : 1.f;
    g_m[n] = m;
    float s = m;
#pragma unroll
    for (int o = 16; o > 0; o >>= 1) s += __shfl_xor_sync(0xffffffffu, s, o);
    __shared__ float red[8];
    int wid = threadIdx.x >> 5, lane = threadIdx.x & 31;
    if (lane == 0) red[wid] = s;
    __syncthreads();
    if (threadIdx.x == 0) {
        float t = 0.f;
        for (int i = 0; i < 8; i++) t += red[i];
        atomicAdd(&g_cm[n >> 13], t);
    }
}

__global__ void k_zero() {
    int i = blockIdx.x * blockDim.x + threadIdx.x;
    if (i < B_ * D_ * D_) g_S[i] = 0.f;
    if (i < B_ * D_) { g_rk[i] = 0.f; g_rv[i] = 0.f; }
    if (i < B_) g_cm[i] = 0.f;
}

// ---------------- k1: S[b] += K_m^T V via tcgen05, fused transpose+convert ----
// grid (16 chunks, 2 slabs, B). Per chunk: 64 n window. 8 windows per CTA.
__global__ void __launch_bounds__(512, 1)
k1_mma(const float* __restrict__ key, const float* __restrict__ value) {
#if TCOK
    extern __shared__ char smem[];
    const u32 sb = smem_u32(smem);
    const int tid = threadIdx.x, wid = tid >> 5, lid = tid & 31;
    const int b = blockIdx.z, slab = blockIdx.y, chunk = blockIdx.x;
    const int d0 = slab * 128;
    const int n_start = chunk * 512;

    if (wid == 0) tmem_alloc(sb + SM_TPTR, 256);
    if (tid == 0) mbar_init(sb + SM_MBAR, 1);
    __syncthreads();
    u32 tbase;
    asm volatile("ld.shared.b32 %0, [%1];" : "=r"(tbase) : "r"(sb + SM_TPTR));

    const ull dAH = mk_desc(sb + K1_AH), dAL = mk_desc(sb + K1_AL);
    const ull dBH = mk_desc(sb + K1_BH), dBL = mk_desc(sb + K1_BL);
    float* stgK = (float*)(smem + K1_STGK);    // [64 n][132] (d-slab cols)
    float* stgV = (float*)(smem + K1_STGV);    // [64 n][260] (e cols)
    float* smv  = (float*)(smem + K1_SMV);     // [64]

    for (int c = 0; c < 8; c++) {
        const int n = n_start + c * 64;
        const float* kp = key + ((size_t)b * N_ + n) * D_ + d0;
        const float* vp = value + ((size_t)b * N_ + n) * D_;
        // stage fp32 tiles (staging not read by MMA -> overlaps prev chunk MMA)
        if (tid < 64) smv[tid] = g_m[(size_t)b * N_ + n + tid];
#pragma unroll
        for (int i = tid; i < 2048; i += 512) {           // key: 64 x 128 f32
            int r = i >> 5, cc = i & 31;
            *(float4*)&stgK[r * 132 + cc * 4] = *(const float4*)(kp + (size_t)r * D_ + cc * 4);
        }
#pragma unroll
        for (int i = tid; i < 4096; i += 512) {           // value: 64 x 256 f32
            int r = i >> 6, cc = i & 63;
            *(float4*)&stgV[r * 260 + cc * 4] = *(const float4*)(vp + (size_t)r * D_ + cc * 4);
        }
        __syncthreads();
        if (c >= 1) mbar_wait(sb + SM_MBAR, (u32)((c - 1) & 1));  // A/B bufs free

        // transpose-convert A: 128 d-rows x 64 n, mask applied
#pragma unroll
        for (int i = tid; i < 1024; i += 512) {
            int r = i & 127, g = i >> 7;      // r: d row, g: 8-n group
            uint4 hv, lv;
            float f0, f1;
            f0 = stgK[(g * 8 + 0) * 132 + r] * smv[g * 8 + 0];
            f1 = stgK[(g * 8 + 1) * 132 + r] * smv[g * 8 + 1];
            cvt2(f0, f1, hv.x, lv.x);
            f0 = stgK[(g * 8 + 2) * 132 + r] * smv[g * 8 + 2];
            f1 = stgK[(g * 8 + 3) * 132 + r] * smv[g * 8 + 3];
            cvt2(f0, f1, hv.y, lv.y);
            f0 = stgK[(g * 8 + 4) * 132 + r] * smv[g * 8 + 4];
            f1 = stgK[(g * 8 + 5) * 132 + r] * smv[g * 8 + 5];
            cvt2(f0, f1, hv.z, lv.z);
            f0 = stgK[(g * 8 + 6) * 132 + r] * smv[g * 8 + 6];
            f1 = stgK[(g * 8 + 7) * 132 + r] * smv[g * 8 + 7];
            cvt2(f0, f1, hv.w, lv.w);
            u32 sw = sw128((u32)(r * 128 + g * 16));
            *(uint4*)(smem + K1_AH + sw) = hv;
            *(uint4*)(smem + K1_AL + sw) = lv;
        }
        // transpose-convert B: 256 e-rows x 64 n
#pragma unroll
        for (int i = tid; i < 2048; i += 512) {
            int r = i & 255, g = i >> 8;
            uint4 hv, lv;
            cvt2(stgV[(g * 8 + 0) * 260 + r], stgV[(g * 8 + 1) * 260 + r], hv.x, lv.x);
            cvt2(stgV[(g * 8 + 2) * 260 + r], stgV[(g * 8 + 3) * 260 + r], hv.y, lv.y);
            cvt2(stgV[(g * 8 + 4) * 260 + r], stgV[(g * 8 + 5) * 260 + r], hv.z, lv.z);
            cvt2(stgV[(g * 8 + 6) * 260 + r], stgV[(g * 8 + 7) * 260 + r], hv.w, lv.w);
            u32 sw = sw128((u32)(r * 128 + g * 16));
            *(uint4*)(smem + K1_BH + sw) = hv;
            *(uint4*)(smem + K1_BL + sw) = lv;
        }
        // side sums from staging
        if (tid < 128) {
            float s = 0.f;
#pragma unroll
            for (int rr = 0; rr < 64; rr++) s += smv[rr] * stgK[rr * 132 + tid];
            atomicAdd(&g_rk[b * D_ + d0 + tid], s);
        } else if (slab == 0 && tid >= 256) {
            int e = tid - 256;
            float s = 0.f;
#pragma unroll
            for (int rr = 0; rr < 64; rr++) s += smv[rr] * stgV[rr * 260 + e];
            atomicAdd(&g_rv[b * D_ + e], s);
        }
        __syncthreads();
        fence_async_proxy();
        if (wid == 0 && elect1()) {
#pragma unroll
            for (int ks = 0; ks < 4; ks++) {
                ull o = (ull)(ks * 2);
                mma_f16_ss(tbase, dAH + o, dBH + o, MMA_IDESC, !(c == 0 && ks == 0));
                mma_f16_ss(tbase, dAH + o, dBL + o, MMA_IDESC, 1);
                mma_f16_ss(tbase, dAL + o, dBH + o, MMA_IDESC, 1);
            }
            mma_commit(sb + SM_MBAR);
        }
        __syncthreads();
    }
    mbar_wait(sb + SM_MBAR, 1);   // commit 7: parity 7&1
    tc_fence_after();

    if (wid < 4) {
        float* dst0 = g_S + ((size_t)b * D_ + d0 + wid * 32 + lid) * D_;
#pragma unroll
        for (int blk = 0; blk < 8; blk++) {
            u32 r[32];
            LDTM32(r, tbase + blk * 32);
            tmem_wait_ld();
#pragma unroll
            for (int cc = 0; cc < 32; cc++)
                atomicAdd(dst0 + blk * 32 + cc, __uint_as_float(r[cc]));
        }
    }
    __syncthreads();
    if (tid == 0) mbar_inval(sb + SM_MBAR);
    __syncthreads();
    if (wid == 0) tmem_dealloc(tbase, 256);
#else
    // FFMA fallback (only for the non-'a' PTX stage; never selected at runtime)
    const int tid = threadIdx.x;
    const int b = blockIdx.z, d0 = blockIdx.y * 128, chunk = blockIdx.x;
    const int n_start = chunk * 512;
    for (int idx = tid; idx < 128 * 256; idx += 512) {
        int d = d0 + (idx >> 8), e = idx & 255;
        float acc = 0.f;
        for (int n = n_start; n < n_start + 512; n++) {
            float m = g_m[(size_t)b * N_ + n];
            acc += m * key[((size_t)b * N_ + n) * D_ + d] * value[((size_t)b * N_ + n) * D_ + e];
        }
        atomicAdd(&g_S[((size_t)b * D_ + d) * D_ + e], acc);
    }
    if (tid < 128) {
        float s = 0.f;
        for (int n = n_start; n < n_start + 512; n++)
            s += g_m[(size_t)b * N_ + n] * key[((size_t)b * N_ + n) * D_ + d0 + tid];
        atomicAdd(&g_rk[b * D_ + d0 + tid], s);
    } else if (blockIdx.y == 0 && tid >= 256) {
        int e = tid - 256;
        float s = 0.f;
        for (int n = n_start; n < n_start + 512; n++)
            s += g_m[(size_t)b * N_ + n] * value[((size_t)b * N_ + n) * D_ + e];
        atomicAdd(&g_rv[b * D_ + e], s);
    }
#endif
}

// ---------------- k_uw: u = Wk@rk, w = Wv@rv ----------------
__global__ void k_uw(const float* __restrict__ Wk, const float* __restrict__ Wv) {
    int b = blockIdx.x, d = threadIdx.x;
    float su = 0.f, sw = 0.f;
    for (int i = 0; i < D_; i++) {
        su += Wk[d * D_ + i] * g_rk[b * D_ + i];
        sw += Wv[d * D_ + i] * g_rv[b * D_ + i];
    }
    g_u[b * D_ + d] = su;
    g_w[b * D_ + d] = sw;
}

// ---------------- k2: T1 = Wk @ S ----------------
__global__ void __launch_bounds__(256, 1)
k2_T1(const float* __restrict__ Wk) {
    const int b = blockIdx.y, d0 = blockIdx.x * 16;
    const int tid = threadIdx.x, tx = tid & 15, ty = tid >> 4;
    __shared__ float sA[16][16];
    __shared__ float sB[16][256];
    ull acc[8];
#pragma unroll
    for (int p = 0; p < 8; p++) acc[p] = 0ull;
    const float* Sb = g_S + b * D_ * D_;
    for (int i0 = 0; i0 < D_; i0 += 16) {
        __syncthreads();
        if (tid < 64) {
            int r = tid >> 2, q = tid & 3;
            *(float4*)&sA[r][q * 4] = *(const float4*)(Wk + (size_t)(d0 + r) * D_ + i0 + q * 4);
        }
#pragma unroll
        for (int i = 0; i < 4; i++) {
            int idx = tid + 256 * i;
            int r = idx >> 6, q = idx & 63;
            *(float4*)&sB[r][q * 4] = *(const float4*)(Sb + (size_t)(i0 + r) * D_ + q * 4);
        }
        __syncthreads();
#pragma unroll
        for (int ii = 0; ii < 16; ii++) {
            float a = sA[ty][ii];
            ull a2 = pack2(a, a);
#pragma unroll
            for (int p = 0; p < 8; p++)
                acc[p] = ffma2(a2, *(const ull*)&sB[ii][2 * tx + 32 * p], acc[p]);
        }
    }
    float* T1b = g_T1 + b * D_ * D_;
    int row = d0 + ty;
#pragma unroll
    for (int p = 0; p < 8; p++) {
        float lo, hi; unpack2(acc[p], lo, hi);
        *(float2*)&T1b[row * D_ + 2 * tx + 32 * p] = make_float2(lo, hi);
    }
}

// ---------------- k3: A = (T1 @ Wv^T + rank-1) / sqrt(8) ----------------
__global__ void __launch_bounds__(256, 1)
k3_A(const float* __restrict__ Wv, const float* __restrict__ bk,
     const float* __restrict__ bv) {
    const int b = blockIdx.y, d0 = blockIdx.x * 16;
    const int tid = threadIdx.x, tx = tid & 15, ty = tid >> 4;
    __shared__ float sA[16][16];
    __shared__ float sB[16][258];
    ull acc[8];
#pragma unroll
    for (int p = 0; p < 8; p++) acc[p] = 0ull;
    const float* T1b = g_T1 + b * D_ * D_;
    for (int j0 = 0; j0 < D_; j0 += 16) {
        __syncthreads();
        if (tid < 64) {
            int r = tid >> 2, q = tid & 3;
            *(float4*)&sA[r][q * 4] = *(const float4*)(T1b + (size_t)(d0 + r) * D_ + j0 + q * 4);
        }
#pragma unroll
        for (int i = 0; i < 4; i++) {
            int idx = tid + 256 * i;
            int q = idx & 3, e = idx >> 2;
            float4 v = *(const float4*)(Wv + (size_t)e * D_ + j0 + q * 4);
            sB[q * 4 + 0][e] = v.x; sB[q * 4 + 1][e] = v.y;
            sB[q * 4 + 2][e] = v.z; sB[q * 4 + 3][e] = v.w;
        }
        __syncthreads();
#pragma unroll
        for (int jj = 0; jj < 16; jj++) {
            float a = sA[ty][jj];
            ull a2 = pack2(a, a);
#pragma unroll
            for (int p = 0; p < 8; p++)
                acc[p] = ffma2(a2, *(const ull*)&sB[jj][2 * tx + 32 * p], acc[p]);
        }
    }
    const int d = d0 + ty;
    const float u_d = g_u[b * D_ + d], bk_d = bk[d], cmv = g_cm[b];
    const float inv = 0.3535533905932738f;
    float* Ab = g_A + b * D_ * D_;
#pragma unroll
    for (int p = 0; p < 8; p++) {
        float lo, hi; unpack2(acc[p], lo, hi);
        int e = 2 * tx + 32 * p;
        float bv0 = bv[e], bv1 = bv[e + 1];
        float w0 = g_w[b * D_ + e], w1 = g_w[b * D_ + e + 1];
        lo = (lo + u_d * bv0 + bk_d * w0 + cmv * bk_d * bv0) * inv;
        hi = (hi + u_d * bv1 + bk_d * w1 + cmv * bk_d * bv1) * inv;
        *(float2*)&Ab[d * D_ + e] = make_float2(lo, hi);
    }
}

// ---------------- k4: column softmax + t = bq^T aw ----------------
__global__ void k4_softmax(const float* __restrict__ bq) {
    const int b = blockIdx.y;
    const int w = threadIdx.x >> 5, lane = threadIdx.x & 31;
    const int e = blockIdx.x * 8 + w;
    float* col = g_A + b * D_ * D_ + e;
    float v[8];
#pragma unroll
    for (int s = 0; s < 8; s++) v[s] = col[(lane + 32 * s) * D_];
    float mx = v[0];
#pragma unroll
    for (int s = 1; s < 8; s++) mx = fmaxf(mx, v[s]);
#pragma unroll
    for (int o = 16; o > 0; o >>= 1) mx = fmaxf(mx, __shfl_xor_sync(0xffffffffu, mx, o));
    float sum = 0.f;
#pragma unroll
    for (int s = 0; s < 8; s++) { v[s] = expf(v[s] - mx); sum += v[s]; }
#pragma unroll
    for (int o = 16; o > 0; o >>= 1) sum += __shfl_xor_sync(0xffffffffu, sum, o);
    const float isum = 1.f / sum;
    float tacc = 0.f;
#pragma unroll
    for (int s = 0; s < 8; s++) {
        float p = v[s] * isum;
        col[(lane + 32 * s) * D_] = p;
        tacc += p * bq[lane + 32 * s];
    }
#pragma unroll
    for (int o = 16; o > 0; o >>= 1) tacc += __shfl_xor_sync(0xffffffffu, tacc, o);
    if (lane == 0) g_t[b * D_ + e] = tacc;
}

// ---------------- k5: M^T[e][i] = sum_d Wq[d][i] aw[d][e] -> bf16 hi/lo ------
__global__ void __launch_bounds__(256, 1)
k5_M(const float* __restrict__ Wq) {
    const int b = blockIdx.y, i0 = blockIdx.x * 16;
    const int tid = threadIdx.x, tx = tid & 15, ty = tid >> 4;
    __shared__ float sA[16][17];
    __shared__ float sB[16][256];
    ull acc[8];
#pragma unroll
    for (int p = 0; p < 8; p++) acc[p] = 0ull;
    const float* awb = g_A + b * D_ * D_;
    for (int dd0 = 0; dd0 < D_; dd0 += 16) {
        __syncthreads();
        if (tid < 64) {
            int r = tid >> 2, q = tid & 3;
            float4 v = *(const float4*)(Wq + (size_t)(dd0 + r) * D_ + i0 + q * 4);
            sA[q * 4 + 0][r] = v.x; sA[q * 4 + 1][r] = v.y;
            sA[q * 4 + 2][r] = v.z; sA[q * 4 + 3][r] = v.w;
        }
#pragma unroll
        for (int i = 0; i < 4; i++) {
            int idx = tid + 256 * i;
            int r = idx >> 6, q = idx & 63;
            *(float4*)&sB[r][q * 4] = *(const float4*)(awb + (size_t)(dd0 + r) * D_ + q * 4);
        }
        __syncthreads();
#pragma unroll
        for (int dd = 0; dd < 16; dd++) {
            float a = sA[ty][dd];
            ull a2 = pack2(a, a);
#pragma unroll
            for (int p = 0; p < 8; p++)
                acc[p] = ffma2(a2, *(const ull*)&sB[dd][2 * tx + 32 * p], acc[p]);
        }
    }
    const int row = i0 + ty;
#pragma unroll
    for (int p = 0; p < 8; p++) {
        float lo, hi; unpack2(acc[p], lo, hi);
        int e0 = 2 * tx + 32 * p, e1 = e0 + 1;
        __nv_bfloat16 h0 = __float2bfloat16(lo);
        __nv_bfloat16 h1 = __float2bfloat16(hi);
        g_MTH[((size_t)b * D_ + e0) * D_ + row] = h0;
        g_MTL[((size_t)b * D_ + e0) * D_ + row] = __float2bfloat16(lo - __bfloat162float(h0));
        g_MTH[((size_t)b * D_ + e1) * D_ + row] = h1;
        g_MTL[((size_t)b * D_ + e1) * D_ + row] = __float2bfloat16(hi - __bfloat162float(h1));
    }
}

// ---------------- k6: out = query @ M + t via tcgen05, fused q conversion ----
__global__ void __launch_bounds__(512, 1)
k6_mma(const float* __restrict__ query, float* __restrict__ out) {
#if TCOK
    extern __shared__ char smem[];
    const u32 sb = smem_u32(smem);
    const int tid = threadIdx.x, wid = tid >> 5, lid = tid & 31;
    const int b = blockIdx.y, n0 = blockIdx.x * 128;

    if (wid == 0) tmem_alloc(sb + SM_TPTR, 256);
    if (tid == 0) mbar_init(sb + SM_MBAR, 1);
    __syncthreads();
    u32 tbase;
    asm volatile("ld.shared.b32 %0, [%1];" : "=r"(tbase) : "r"(sb + SM_TPTR));

    const ull dAH = mk_desc(sb + SM_AH), dAL = mk_desc(sb + SM_AL);
    const ull dBH = mk_desc(sb + SM_BH), dBL = mk_desc(sb + SM_BL);
    const float* qb = query + ((size_t)b * N_ + n0) * D_;
    const size_t bbase0 = (size_t)b * D_ * D_;

    for (int c = 0; c < 4; c++) {
        if (c >= 1) mbar_wait(sb + SM_MBAR, (u32)((c - 1) & 1));
        const int dc = c * 64;
#pragma unroll
        for (int i = tid; i < 1024; i += 512) {           // A: q fp32 -> hi/lo inline
            int r = i >> 3, c16 = i & 7;
            const float* src = qb + (size_t)r * D_ + dc + c16 * 8;
            float4 a = *(const float4*)(src);
            float4 d = *(const float4*)(src + 4);
            uint4 hv, lv;
            cvt2(a.x, a.y, hv.x, lv.x);
            cvt2(a.z, a.w, hv.y, lv.y);
            cvt2(d.x, d.y, hv.z, lv.z);
            cvt2(d.z, d.w, hv.w, lv.w);
            u32 sw = sw128((u32)(r * 128 + c16 * 16));
            *(uint4*)(smem + SM_AH + sw) = hv;
            *(uint4*)(smem + SM_AL + sw) = lv;
        }
#pragma unroll
        for (int i = tid; i < 2048; i += 512) {           // B: M^T bf16 rows
            int r = i >> 3, c16 = i & 7;
            size_t off = bbase0 + (size_t)r * D_ + dc + c16 * 8;
            u32 sw = sw128((u32)(r * 128 + c16 * 16));
            *(uint4*)(smem + SM_BH + sw) = *(const uint4*)(g_MTH + off);
            *(uint4*)(smem + SM_BL + sw) = *(const uint4*)(g_MTL + off);
        }
        __syncthreads();
        fence_async_proxy();
        if (wid == 0 && elect1()) {
#pragma unroll
            for (int ks = 0; ks < 4; ks++) {
                ull o = (ull)(ks * 2);
                mma_f16_ss(tbase, dAH + o, dBH + o, MMA_IDESC, !(c == 0 && ks == 0));
                mma_f16_ss(tbase, dAH + o, dBL + o, MMA_IDESC, 1);
                mma_f16_ss(tbase, dAL + o, dBH + o, MMA_IDESC, 1);
            }
            mma_commit(sb + SM_MBAR);
        }
        __syncthreads();
    }
    mbar_wait(sb + SM_MBAR, 1);    // commit 3: parity 3&1
    tc_fence_after();

    float* stage = (float*)(smem + 1024);   // [128][68]
    for (int cb = 0; cb < 4; cb++) {
        __syncthreads();
        if (wid < 4) {
            u32 r0[32], r1[32];
            LDTM32(r0, tbase + cb * 64);
            LDTM32(r1, tbase + cb * 64 + 32);
            tmem_wait_ld();
            float* srow = stage + (wid * 32 + lid) * 68;
#pragma unroll
            for (int cc = 0; cc < 32; cc++) {
                srow[cc] = __uint_as_float(r0[cc]);
                srow[32 + cc] = __uint_as_float(r1[cc]);
            }
        }
        __syncthreads();
#pragma unroll
        for (int i = tid; i < 2048; i += 512) {
            int r = i >> 4, c4 = i & 15;
            float4 v = *(float4*)(stage + r * 68 + c4 * 4);
            int e = cb * 64 + c4 * 4;
            v.x += g_t[b * D_ + e];
            v.y += g_t[b * D_ + e + 1];
            v.z += g_t[b * D_ + e + 2];
            v.w += g_t[b * D_ + e + 3];
            *(float4*)(out + ((size_t)b * N_ + n0 + r) * D_ + e) = v;
        }
    }
    __syncthreads();
    if (tid == 0) mbar_inval(sb + SM_MBAR);
    __syncthreads();
    if (wid == 0) tmem_dealloc(tbase, 256);
#else
    // FFMA fallback
    const int tid = threadIdx.x;
    const int b = blockIdx.y, n0 = blockIdx.x * 128;
    for (int idx = tid; idx < 128 * 256; idx += 512) {
        int n = n0 + (idx >> 8), e = idx & 255;
        const float* q = query + ((size_t)b * N_ + n) * D_;
        const __nv_bfloat16* mh = g_MTH + ((size_t)b * D_ + e) * D_;
        const __nv_bfloat16* ml = g_MTL + ((size_t)b * D_ + e) * D_;
        float acc = g_t[b * D_ + e];
        for (int d = 0; d < D_; d++)
            acc += q[d] * (__bfloat162float(mh[d]) + __bfloat162float(ml[d]));
        out[((size_t)b * N_ + n) * D_ + e] = acc;
    }
#endif
}

// ---------------- launch ----------------
extern "C" void kernel_launch(void* const* d_in, const int* in_sizes, int n_in,
                              void* d_out, int out_size) {
    const float* query = (const float*)d_in[0];
    const float* key   = (const float*)d_in[1];
    const float* value = (const float*)d_in[2];
    const void*  maskraw = d_in[3];
    int o = (n_in >= 11) ? 5 : 4;
    const float* Wq = (const float*)d_in[o + 0];
    const float* bq = (const float*)d_in[o + 1];
    const float* Wk = (const float*)d_in[o + 2];
    const float* bk = (const float*)d_in[o + 3];
    const float* Wv = (const float*)d_in[o + 4];
    const float* bv = (const float*)d_in[o + 5];
    float* out = (float*)d_out;
    (void)in_sizes; (void)out_size;

    cudaFuncSetAttribute(k1_mma, cudaFuncAttributeMaxDynamicSharedMemorySize, K1_TOTAL);
    cudaFuncSetAttribute(k6_mma, cudaFuncAttributeMaxDynamicSharedMemorySize, SMEM_TOTAL);

    k_zero<<<(B_ * D_ * D_ + 255) / 256, 256>>>();
    k_detect<<<1, 256>>>((const unsigned char*)maskraw);
    k_maskconv<<<(B_ * N_) / 256, 256>>>(maskraw);
    k1_mma<<<dim3(16, 2, B_), 512, K1_TOTAL>>>(key, value);
    k_uw<<<B_, 256>>>(Wk, Wv);
    k2_T1<<<dim3(16, B_), 256>>>(Wk);
    k3_A<<<dim3(16, B_), 256>>>(Wv, bk, bv);
    k4_softmax<<<dim3(32, B_), 256>>>(bq);
    k5_M<<<dim3(16, B_), 256>>>(Wq);
    k6_mma<<<dim3(64, B_), 512, SMEM_TOTAL>>>(query, out);
}